// round 4
// baseline (speedup 1.0000x reference)
#include <cuda_runtime.h>

#define H     51
#define NJG   26          // j row-pair groups (52 rows, row 51 = zeros)
#define PAIRF 176         // floats per row-pair (2*80 + 16 pad) -> 44 units == 4 mod 8
#define QF    20          // floats per k-quarter slot (14 data + 6 pad) -> 5 units
#define HROW  80          // floats per state vector (4 quarters)
#define WMAT  (NJG*PAIRF) // 4576 floats per gate matrix
#define E     16
#define TPB   416         // 26 jg * 4 eg * 4 kq
#define XCH   40
#define B_TOT 2048

typedef unsigned long long ull;

struct __align__(16) Smem {
    float l1r[WMAT], l1z[WMAT], l1n[WMAT];   // w_hh1 gates
    float ir2[WMAT], iz2[WMAT], in2[WMAT];   // w_ih2 gates
    float hr2[WMAT], hz2[WMAT], hn2[WMAT];   // w_hh2 gates
    float wih1r[52], wih1z[52], wih1n[52];
    float bR1[52], bZ1[52], bIN1[52], bHN1[52];
    float bR2[52], bZ2[52], bIN2[52], bHN2[52];
    float wlinP[HROW];                        // quarter-padded, pads 0
    float h1[2][E][HROW];                     // ping-pong, pads stay 0
    float h2[2][E][HROW];
    float xbuf[E][XCH];
    float outp[E];
    float blin;
};

__device__ __forceinline__ void fma2(ull& d, ull a, ull b) {
    asm("fma.rn.f32x2 %0, %1, %2, %0;" : "+l"(d) : "l"(a), "l"(b));
}
__device__ __forceinline__ ull pack2(float a, float b) {
    ull r; asm("mov.b64 %0, {%1,%2};" : "=l"(r) : "f"(a), "f"(b)); return r;
}
__device__ __forceinline__ float sum2(ull v) {
    float a, b; asm("mov.b64 {%0,%1}, %2;" : "=f"(a), "=f"(b) : "l"(v));
    return a + b;
}
__device__ __forceinline__ float sigmoid_(float v) {
    return __fdividef(1.0f, 1.0f + __expf(-v));
}
__device__ __forceinline__ float tanh_(float v) {
    return __fdividef(2.0f, 1.0f + __expf(-2.0f * v)) - 1.0f;
}
__device__ __forceinline__ float gru_cell(float gr, float gz, float gin,
                                          float ghn, float ho) {
    float r = sigmoid_(gr);
    float z = sigmoid_(gz);
    float n = tanh_(fmaf(r, ghn, gin));
    return fmaf(z, ho - n, n);
}
// cross-kq transpose-reduce: lane (kq) returns sum over the 4 k-quarters of v[kq]
__device__ __forceinline__ float xreduce4(float v0, float v1, float v2, float v3,
                                          bool b0, bool b1) {
    float sa = b0 ? v0 : v1;      // send slot (1-b0)
    float sb = b0 ? v2 : v3;      // send slot 2|(1-b0)
    float ka = b0 ? v1 : v0;      // keep slot b0
    float kb = b0 ? v3 : v2;      // keep slot 2|b0
    float p0 = ka + __shfl_xor_sync(0xFFFFFFFFu, sa, 1);
    float p1 = kb + __shfl_xor_sync(0xFFFFFFFFu, sb, 1);
    float sd = b1 ? p0 : p1;
    float kp = b1 ? p1 : p0;
    return kp + __shfl_xor_sync(0xFFFFFFFFu, sd, 2);
}

__global__ void __launch_bounds__(TPB, 1) gru_stack_kernel(
    const float* __restrict__ x,
    const float* __restrict__ w_ih1, const float* __restrict__ w_hh1,
    const float* __restrict__ b_ih1, const float* __restrict__ b_hh1,
    const float* __restrict__ w_ih2, const float* __restrict__ w_hh2,
    const float* __restrict__ b_ih2, const float* __restrict__ b_hh2,
    const float* __restrict__ w_lin, const float* __restrict__ b_lin,
    float* __restrict__ out, int T, int F)
{
    extern __shared__ float smem_f[];
    Smem* s = reinterpret_cast<Smem*>(smem_f);

    const int tid = threadIdx.x;
    const int kq  = tid & 3;
    const int eg  = (tid >> 2) & 3;
    const int jg  = tid >> 4;               // 0..25
    const bool b0 = (kq & 1) != 0;
    const bool b1 = (kq & 2) != 0;
    const int j0  = 2 * jg;
    const int el  = eg + 4 * kq;            // activation element for this lane
    const int pos0 = (j0 / 14) * QF + (j0 % 14); // h position of j0 (j0,j0+1 adjacent)
    const int base = blockIdx.x * E;
    const int TF   = T + F;

    // ---------------- one-time init ----------------
    for (int idx = tid; idx < WMAT; idx += TPB) {
        int jgx = idx / PAIRF, r = idx - jgx * PAIRF;
        int jj = r / HROW;                  // 0,1, or 2 (pair pad)
        int w  = r - jj * HROW;
        int q  = w / QF, i = w - q * QF;
        int j  = 2 * jgx + jj, k = q * 14 + i;
        bool valid = (jj < 2) && (i < 14) && (k < H) && (j < H);
        int o0 = valid ? (j * H + k) : 0;
        s->l1r[idx] = valid ? w_hh1[o0] : 0.f;
        s->l1z[idx] = valid ? w_hh1[(H * H) + o0] : 0.f;
        s->l1n[idx] = valid ? w_hh1[(2 * H * H) + o0] : 0.f;
        s->ir2[idx] = valid ? w_ih2[o0] : 0.f;
        s->iz2[idx] = valid ? w_ih2[(H * H) + o0] : 0.f;
        s->in2[idx] = valid ? w_ih2[(2 * H * H) + o0] : 0.f;
        s->hr2[idx] = valid ? w_hh2[o0] : 0.f;
        s->hz2[idx] = valid ? w_hh2[(H * H) + o0] : 0.f;
        s->hn2[idx] = valid ? w_hh2[(2 * H * H) + o0] : 0.f;
    }
    for (int i = tid; i < 52; i += TPB) {
        bool v = (i < H);
        s->wih1r[i] = v ? w_ih1[i] : 0.f;
        s->wih1z[i] = v ? w_ih1[H + i] : 0.f;
        s->wih1n[i] = v ? w_ih1[2 * H + i] : 0.f;
        s->bR1[i]  = v ? (b_ih1[i] + b_hh1[i]) : 0.f;
        s->bZ1[i]  = v ? (b_ih1[H + i] + b_hh1[H + i]) : 0.f;
        s->bIN1[i] = v ? b_ih1[2 * H + i] : 0.f;
        s->bHN1[i] = v ? b_hh1[2 * H + i] : 0.f;
        s->bR2[i]  = v ? (b_ih2[i] + b_hh2[i]) : 0.f;
        s->bZ2[i]  = v ? (b_ih2[H + i] + b_hh2[H + i]) : 0.f;
        s->bIN2[i] = v ? b_ih2[2 * H + i] : 0.f;
        s->bHN2[i] = v ? b_hh2[2 * H + i] : 0.f;
    }
    for (int i = tid; i < HROW; i += TPB) {
        int q = i / QF, ii = i - q * QF, k = q * 14 + ii;
        s->wlinP[i] = (ii < 14 && k < H) ? w_lin[k] : 0.f;
    }
    if (tid == 0) s->blin = b_lin[0];
    {
        float* h1f = &s->h1[0][0][0];
        float* h2f = &s->h2[0][0][0];
        for (int i = tid; i < 2 * E * HROW; i += TPB) { h1f[i] = 0.f; h2f[i] = 0.f; }
        for (int i = tid; i < E; i += TPB) s->outp[i] = 0.f;
    }
    __syncthreads();

    int cur = 0;
    for (int t = 0; t < TF; ++t) {
        const int nxt = cur ^ 1;
        if (t < T && (t % XCH) == 0) {
            for (int i = tid; i < E * XCH; i += TPB) {
                int e = i / XCH, c = i - e * XCH;
                int tg = t + c;
                s->xbuf[e][c] = (tg < T) ? x[(size_t)(base + e) * T + tg] : 0.f;
            }
            __syncthreads();
        }
        const int xidx = t % XCH;

        // -------- A: output linear for step t-1 (overlaps L1 in phase 1) --------
        if (t > 0 && tid < E) {
            const ulonglong2* hv = (const ulonglong2*)&s->h2[cur][tid][0];
            const ulonglong2* wl = (const ulonglong2*)s->wlinP;
            ull acc = pack2(s->blin, 0.f);
            #pragma unroll
            for (int k = 0; k < HROW / 4; k++) {
                ulonglong2 h = hv[k], w = wl[k];
                fma2(acc, h.x, w.x); fma2(acc, h.y, w.y);
            }
            float o = sum2(acc);
            out[(size_t)(base + tid) * TF + (t - 1)] = o;
            s->outp[tid] = o;
        }
        if (t >= T) __syncthreads();   // phase 2: outp feeds L1

        // ======================= layer 1 =======================
        {
            ull aR[2][4], aZ[2][4], aN[2][4];
            {
                float2 br = *(const float2*)&s->bR1[j0];
                float2 bz = *(const float2*)&s->bZ1[j0];
                float2 bn = *(const float2*)&s->bHN1[j0];
                #pragma unroll
                for (int ei = 0; ei < 4; ei++) {
                    aR[0][ei] = (kq == 0) ? pack2(br.x, 0.f) : 0ull;
                    aR[1][ei] = (kq == 0) ? pack2(br.y, 0.f) : 0ull;
                    aZ[0][ei] = (kq == 0) ? pack2(bz.x, 0.f) : 0ull;
                    aZ[1][ei] = (kq == 0) ? pack2(bz.y, 0.f) : 0ull;
                    aN[0][ei] = (kq == 0) ? pack2(bn.x, 0.f) : 0ull;
                    aN[1][ei] = (kq == 0) ? pack2(bn.y, 0.f) : 0ull;
                }
            }
            const float* wrB = s->l1r + jg * PAIRF + kq * QF;
            const float* wzB = s->l1z + jg * PAIRF + kq * QF;
            const float* wnB = s->l1n + jg * PAIRF + kq * QF;
            const float* hB  = &s->h1[cur][0][0] + eg * HROW + kq * QF;
            #pragma unroll
            for (int ki = 0; ki < 3; ki++) {
                ulonglong2 r0 = ((const ulonglong2*)wrB)[ki];
                ulonglong2 r1 = ((const ulonglong2*)(wrB + HROW))[ki];
                ulonglong2 z0 = ((const ulonglong2*)wzB)[ki];
                ulonglong2 z1 = ((const ulonglong2*)(wzB + HROW))[ki];
                ulonglong2 n0 = ((const ulonglong2*)wnB)[ki];
                ulonglong2 n1 = ((const ulonglong2*)(wnB + HROW))[ki];
                #pragma unroll
                for (int ei = 0; ei < 4; ei++) {
                    ulonglong2 h = ((const ulonglong2*)(hB + ei * 4 * HROW))[ki];
                    fma2(aR[0][ei], h.x, r0.x); fma2(aR[0][ei], h.y, r0.y);
                    fma2(aR[1][ei], h.x, r1.x); fma2(aR[1][ei], h.y, r1.y);
                    fma2(aZ[0][ei], h.x, z0.x); fma2(aZ[0][ei], h.y, z0.y);
                    fma2(aZ[1][ei], h.x, z1.x); fma2(aZ[1][ei], h.y, z1.y);
                    fma2(aN[0][ei], h.x, n0.x); fma2(aN[0][ei], h.y, n0.y);
                    fma2(aN[1][ei], h.x, n1.x); fma2(aN[1][ei], h.y, n1.y);
                }
            }
            {   // tail: floats 12,13 of the quarter
                ull r0 = *(const ull*)(wrB + 12), r1 = *(const ull*)(wrB + HROW + 12);
                ull z0 = *(const ull*)(wzB + 12), z1 = *(const ull*)(wzB + HROW + 12);
                ull n0 = *(const ull*)(wnB + 12), n1 = *(const ull*)(wnB + HROW + 12);
                #pragma unroll
                for (int ei = 0; ei < 4; ei++) {
                    ull h = *(const ull*)(hB + ei * 4 * HROW + 12);
                    fma2(aR[0][ei], h, r0); fma2(aR[1][ei], h, r1);
                    fma2(aZ[0][ei], h, z0); fma2(aZ[1][ei], h, z1);
                    fma2(aN[0][ei], h, n0); fma2(aN[1][ei], h, n1);
                }
            }
            float gr0 = xreduce4(sum2(aR[0][0]), sum2(aR[0][1]), sum2(aR[0][2]), sum2(aR[0][3]), b0, b1);
            float gr1 = xreduce4(sum2(aR[1][0]), sum2(aR[1][1]), sum2(aR[1][2]), sum2(aR[1][3]), b0, b1);
            float gz0 = xreduce4(sum2(aZ[0][0]), sum2(aZ[0][1]), sum2(aZ[0][2]), sum2(aZ[0][3]), b0, b1);
            float gz1 = xreduce4(sum2(aZ[1][0]), sum2(aZ[1][1]), sum2(aZ[1][2]), sum2(aZ[1][3]), b0, b1);
            float gn0 = xreduce4(sum2(aN[0][0]), sum2(aN[0][1]), sum2(aN[0][2]), sum2(aN[0][3]), b0, b1);
            float gn1 = xreduce4(sum2(aN[1][0]), sum2(aN[1][1]), sum2(aN[1][2]), sum2(aN[1][3]), b0, b1);

            float xv = (t < T) ? s->xbuf[el][xidx] : s->outp[el];
            float2 wr = *(const float2*)&s->wih1r[j0];
            float2 wz = *(const float2*)&s->wih1z[j0];
            float2 wn = *(const float2*)&s->wih1n[j0];
            float2 bi = *(const float2*)&s->bIN1[j0];
            float2 ho = *(const float2*)&s->h1[cur][el][pos0];
            float nh0 = gru_cell(fmaf(xv, wr.x, gr0), fmaf(xv, wz.x, gz0),
                                 fmaf(xv, wn.x, bi.x), gn0, ho.x);
            float nh1 = gru_cell(fmaf(xv, wr.y, gr1), fmaf(xv, wz.y, gz1),
                                 fmaf(xv, wn.y, bi.y), gn1, ho.y);
            *(float2*)&s->h1[nxt][el][pos0] = make_float2(nh0, nh1);
        }
        __syncthreads();

        // ======================= layer 2 =======================
        {
            const float* uB = &s->h1[nxt][0][0] + eg * HROW + kq * QF;
            const float* vB = &s->h2[cur][0][0] + eg * HROW + kq * QF;
            float gr0, gr1, gz0, gz1;
            {   // ---- pass RZ ----
                ull aR[2][4], aZ[2][4];
                float2 br = *(const float2*)&s->bR2[j0];
                float2 bz = *(const float2*)&s->bZ2[j0];
                #pragma unroll
                for (int ei = 0; ei < 4; ei++) {
                    aR[0][ei] = (kq == 0) ? pack2(br.x, 0.f) : 0ull;
                    aR[1][ei] = (kq == 0) ? pack2(br.y, 0.f) : 0ull;
                    aZ[0][ei] = (kq == 0) ? pack2(bz.x, 0.f) : 0ull;
                    aZ[1][ei] = (kq == 0) ? pack2(bz.y, 0.f) : 0ull;
                }
                const float* irB = s->ir2 + jg * PAIRF + kq * QF;
                const float* izB = s->iz2 + jg * PAIRF + kq * QF;
                const float* hrB = s->hr2 + jg * PAIRF + kq * QF;
                const float* hzB = s->hz2 + jg * PAIRF + kq * QF;
                #pragma unroll
                for (int ki = 0; ki < 3; ki++) {
                    ulonglong2 i0 = ((const ulonglong2*)irB)[ki];
                    ulonglong2 i1 = ((const ulonglong2*)(irB + HROW))[ki];
                    ulonglong2 j0v = ((const ulonglong2*)izB)[ki];
                    ulonglong2 j1v = ((const ulonglong2*)(izB + HROW))[ki];
                    ulonglong2 p0 = ((const ulonglong2*)hrB)[ki];
                    ulonglong2 p1 = ((const ulonglong2*)(hrB + HROW))[ki];
                    ulonglong2 q0 = ((const ulonglong2*)hzB)[ki];
                    ulonglong2 q1 = ((const ulonglong2*)(hzB + HROW))[ki];
                    #pragma unroll
                    for (int ei = 0; ei < 4; ei++) {
                        ulonglong2 u = ((const ulonglong2*)(uB + ei * 4 * HROW))[ki];
                        ulonglong2 v = ((const ulonglong2*)(vB + ei * 4 * HROW))[ki];
                        fma2(aR[0][ei], u.x, i0.x);  fma2(aR[0][ei], u.y, i0.y);
                        fma2(aR[0][ei], v.x, p0.x);  fma2(aR[0][ei], v.y, p0.y);
                        fma2(aR[1][ei], u.x, i1.x);  fma2(aR[1][ei], u.y, i1.y);
                        fma2(aR[1][ei], v.x, p1.x);  fma2(aR[1][ei], v.y, p1.y);
                        fma2(aZ[0][ei], u.x, j0v.x); fma2(aZ[0][ei], u.y, j0v.y);
                        fma2(aZ[0][ei], v.x, q0.x);  fma2(aZ[0][ei], v.y, q0.y);
                        fma2(aZ[1][ei], u.x, j1v.x); fma2(aZ[1][ei], u.y, j1v.y);
                        fma2(aZ[1][ei], v.x, q1.x);  fma2(aZ[1][ei], v.y, q1.y);
                    }
                }
                {
                    ull i0 = *(const ull*)(irB + 12), i1 = *(const ull*)(irB + HROW + 12);
                    ull z0 = *(const ull*)(izB + 12), z1 = *(const ull*)(izB + HROW + 12);
                    ull p0 = *(const ull*)(hrB + 12), p1 = *(const ull*)(hrB + HROW + 12);
                    ull q0 = *(const ull*)(hzB + 12), q1 = *(const ull*)(hzB + HROW + 12);
                    #pragma unroll
                    for (int ei = 0; ei < 4; ei++) {
                        ull u = *(const ull*)(uB + ei * 4 * HROW + 12);
                        ull v = *(const ull*)(vB + ei * 4 * HROW + 12);
                        fma2(aR[0][ei], u, i0); fma2(aR[0][ei], v, p0);
                        fma2(aR[1][ei], u, i1); fma2(aR[1][ei], v, p1);
                        fma2(aZ[0][ei], u, z0); fma2(aZ[0][ei], v, q0);
                        fma2(aZ[1][ei], u, z1); fma2(aZ[1][ei], v, q1);
                    }
                }
                gr0 = xreduce4(sum2(aR[0][0]), sum2(aR[0][1]), sum2(aR[0][2]), sum2(aR[0][3]), b0, b1);
                gr1 = xreduce4(sum2(aR[1][0]), sum2(aR[1][1]), sum2(aR[1][2]), sum2(aR[1][3]), b0, b1);
                gz0 = xreduce4(sum2(aZ[0][0]), sum2(aZ[0][1]), sum2(aZ[0][2]), sum2(aZ[0][3]), b0, b1);
                gz1 = xreduce4(sum2(aZ[1][0]), sum2(aZ[1][1]), sum2(aZ[1][2]), sum2(aZ[1][3]), b0, b1);
            }
            float gi0, gi1, gh0, gh1;
            {   // ---- pass N ----
                ull aI[2][4], aH[2][4];
                float2 bi = *(const float2*)&s->bIN2[j0];
                float2 bh = *(const float2*)&s->bHN2[j0];
                #pragma unroll
                for (int ei = 0; ei < 4; ei++) {
                    aI[0][ei] = (kq == 0) ? pack2(bi.x, 0.f) : 0ull;
                    aI[1][ei] = (kq == 0) ? pack2(bi.y, 0.f) : 0ull;
                    aH[0][ei] = (kq == 0) ? pack2(bh.x, 0.f) : 0ull;
                    aH[1][ei] = (kq == 0) ? pack2(bh.y, 0.f) : 0ull;
                }
                const float* inB = s->in2 + jg * PAIRF + kq * QF;
                const float* hnB = s->hn2 + jg * PAIRF + kq * QF;
                #pragma unroll
                for (int ki = 0; ki < 3; ki++) {
                    ulonglong2 n0 = ((const ulonglong2*)inB)[ki];
                    ulonglong2 n1 = ((const ulonglong2*)(inB + HROW))[ki];
                    ulonglong2 m0 = ((const ulonglong2*)hnB)[ki];
                    ulonglong2 m1 = ((const ulonglong2*)(hnB + HROW))[ki];
                    #pragma unroll
                    for (int ei = 0; ei < 4; ei++) {
                        ulonglong2 u = ((const ulonglong2*)(uB + ei * 4 * HROW))[ki];
                        ulonglong2 v = ((const ulonglong2*)(vB + ei * 4 * HROW))[ki];
                        fma2(aI[0][ei], u.x, n0.x); fma2(aI[0][ei], u.y, n0.y);
                        fma2(aI[1][ei], u.x, n1.x); fma2(aI[1][ei], u.y, n1.y);
                        fma2(aH[0][ei], v.x, m0.x); fma2(aH[0][ei], v.y, m0.y);
                        fma2(aH[1][ei], v.x, m1.x); fma2(aH[1][ei], v.y, m1.y);
                    }
                }
                {
                    ull n0 = *(const ull*)(inB + 12), n1 = *(const ull*)(inB + HROW + 12);
                    ull m0 = *(const ull*)(hnB + 12), m1 = *(const ull*)(hnB + HROW + 12);
                    #pragma unroll
                    for (int ei = 0; ei < 4; ei++) {
                        ull u = *(const ull*)(uB + ei * 4 * HROW + 12);
                        ull v = *(const ull*)(vB + ei * 4 * HROW + 12);
                        fma2(aI[0][ei], u, n0); fma2(aI[1][ei], u, n1);
                        fma2(aH[0][ei], v, m0); fma2(aH[1][ei], v, m1);
                    }
                }
                gi0 = xreduce4(sum2(aI[0][0]), sum2(aI[0][1]), sum2(aI[0][2]), sum2(aI[0][3]), b0, b1);
                gi1 = xreduce4(sum2(aI[1][0]), sum2(aI[1][1]), sum2(aI[1][2]), sum2(aI[1][3]), b0, b1);
                gh0 = xreduce4(sum2(aH[0][0]), sum2(aH[0][1]), sum2(aH[0][2]), sum2(aH[0][3]), b0, b1);
                gh1 = xreduce4(sum2(aH[1][0]), sum2(aH[1][1]), sum2(aH[1][2]), sum2(aH[1][3]), b0, b1);
            }
            float2 ho = *(const float2*)&s->h2[cur][el][pos0];
            float nh0 = gru_cell(gr0, gz0, gi0, gh0, ho.x);
            float nh1 = gru_cell(gr1, gz1, gi1, gh1, ho.y);
            *(float2*)&s->h2[nxt][el][pos0] = make_float2(nh0, nh1);
        }
        __syncthreads();

        cur = nxt;
    }

    // final output (step TF-1)
    if (tid < E) {
        const ulonglong2* hv = (const ulonglong2*)&s->h2[cur][tid][0];
        const ulonglong2* wl = (const ulonglong2*)s->wlinP;
        ull acc = pack2(s->blin, 0.f);
        #pragma unroll
        for (int k = 0; k < HROW / 4; k++) {
            ulonglong2 h = hv[k], w = wl[k];
            fma2(acc, h.x, w.x); fma2(acc, h.y, w.y);
        }
        out[(size_t)(base + tid) * TF + (TF - 1)] = sum2(acc);
    }
}

extern "C" void kernel_launch(void* const* d_in, const int* in_sizes, int n_in,
                              void* d_out, int out_size)
{
    const float* x     = (const float*)d_in[0];
    const float* w_ih1 = (const float*)d_in[1];
    const float* w_hh1 = (const float*)d_in[2];
    const float* b_ih1 = (const float*)d_in[3];
    const float* b_hh1 = (const float*)d_in[4];
    const float* w_ih2 = (const float*)d_in[5];
    const float* w_hh2 = (const float*)d_in[6];
    const float* b_ih2 = (const float*)d_in[7];
    const float* b_hh2 = (const float*)d_in[8];
    const float* w_lin = (const float*)d_in[9];
    const float* b_lin = (const float*)d_in[10];

    const int B  = B_TOT;
    const int T  = in_sizes[0] / B;
    const int TF = out_size / B;
    const int F  = TF - T;

    size_t shmem = sizeof(Smem);
    cudaFuncSetAttribute(gru_stack_kernel,
                         cudaFuncAttributeMaxDynamicSharedMemorySize, (int)shmem);

    gru_stack_kernel<<<B / E, TPB, shmem>>>(
        x, w_ih1, w_hh1, b_ih1, b_hh1,
        w_ih2, w_hh2, b_ih2, b_hh2,
        w_lin, b_lin, (float*)d_out, T, F);
}